// round 14
// baseline (speedup 1.0000x reference)
#include <cuda_runtime.h>

#define EPSF 1e-7f
#define P_TOT 900
#define NCH 144
#define COUT 32
#define L2E 1.4426950408889634f

// Scratch (no allocations allowed)
static __device__ float g_zz[P_TOT * NCH * COUT];   // [p][n][c], log2-scaled
static __device__ float g_C2[NCH * COUT];           // per-(n,c) softmax log2-normalizer
static __device__ float g_W4[NCH * COUT * 16];      // [n][k][c][j] coalesced

__device__ __forceinline__ float ex2(float x) {
    float r; asm("ex2.approx.f32 %0,%1;" : "=f"(r) : "f"(x)); return r;
}
__device__ __forceinline__ float lg2(float x) {
    float r; asm("lg2.approx.f32 %0,%1;" : "=f"(r) : "f"(x)); return r;
}

// W[(n*32+c)*16 + k*4 + j] -> W4[((n*4+k)*32 + c)*4 + j]
__global__ void __launch_bounds__(256) wtrans_kernel(const float* __restrict__ W) {
    int t = blockIdx.x * 256 + threadIdx.x;   // over 144*32*4 float4 rows
    if (t < NCH * COUT * 4) {
        int k = t & 3, c = (t >> 2) & 31, n = t >> 7;
        float4 v = reinterpret_cast<const float4*>(W)[t];
        reinterpret_cast<float4*>(g_W4)[(n * 4 + k) * 32 + c] = v;
    }
}

// CTA = 128 threads = 4 warps = ONE parent; warp w handles children
// n in [36w, 36w+36). lane = c. Per n each warp issues 4 fully coalesced
// LDG.128 (512B contiguous) from W4 (no prefetch: regs <= 85 so 6 CTAs/SM
// fit -> 888 of 900 CTAs resident in wave 1, killing the wave tail).
// rr is never materialized: rr = ex2(zz2 - C2) on the MUFU pipe.
// MODE 0: rr uniform (unweighted sums), M+E.
// MODE 1: rr on the fly, M+E.   MODE 2: rr on the fly, M only, outputs.
template<int MODE>
__global__ void __launch_bounds__(128, 6) me_kernel(
    const float* __restrict__ pose,
    const float* __restrict__ beta_a, const float* __restrict__ beta_v,
    float* __restrict__ out, float lambd)
{
    __shared__ float sA[NCH * 16];            // child poses
    __shared__ float sPart[4][2][512];        // [warp][s/q][e*32+c]
    __shared__ float sRs[4][32];              // [warp][c]

    const int t = threadIdx.x;
    const int lane = t & 31, w = t >> 5;
    const int p = blockIdx.x;
    const int pr = p / 30, pcl = p % 30;

    // gather child poses (float4, 64B rows)
    for (int idx = t; idx < NCH * 4; idx += 128) {
        int n = idx >> 2, vq = idx & 3;
        int k = n >> 4, ci = n & 15;
        int q = (pr + k / 3) * 32 + pcl + (k % 3);
        float4 val = reinterpret_cast<const float4*>(pose + q * 256 + ci * 16)[vq];
        *reinterpret_cast<float4*>(&sA[n * 16 + vq * 4]) = val;
    }
    __syncthreads();

    const int c = lane;
    const float4* W4 = reinterpret_cast<const float4*>(g_W4) + c;   // + n*128 + k*32
    const float* zzr = g_zz + (size_t)p * 4608 + lane;              // + n*32
    const float* c2r = g_C2 + lane;                                 // + n*32
    const int n0 = w * 36;

    // ---- M step over 36 children (direct loads, TLP hides latency) ----
    float s[16], q[16];
#pragma unroll
    for (int e = 0; e < 16; e++) { s[e] = 0.f; q[e] = 0.f; }
    float rs = 0.f;

#pragma unroll 2
    for (int nn = 0; nn < 36; nn++) {
        const int n = n0 + nn;
        const float4* q4 = W4 + n * 128;
        float4 cw0 = q4[0], cw1 = q4[32], cw2 = q4[64], cw3 = q4[96];
        float crr;
        if (MODE != 0) {
            crr = ex2(__ldg(zzr + n * 32) - __ldg(c2r + n * 32));
            rs += crr;
        }
        const float4* Ap = reinterpret_cast<const float4*>(sA + n * 16);
#pragma unroll
        for (int i = 0; i < 4; i++) {
            float4 a = Ap[i];
            float vx = a.x * cw0.x + a.y * cw1.x + a.z * cw2.x + a.w * cw3.x;
            float vy = a.x * cw0.y + a.y * cw1.y + a.z * cw2.y + a.w * cw3.y;
            float vz = a.x * cw0.z + a.y * cw1.z + a.z * cw2.z + a.w * cw3.z;
            float vw = a.x * cw0.w + a.y * cw1.w + a.z * cw2.w + a.w * cw3.w;
            if (MODE == 0) {
                s[i*4+0] += vx; q[i*4+0] += vx * vx;
                s[i*4+1] += vy; q[i*4+1] += vy * vy;
                s[i*4+2] += vz; q[i*4+2] += vz * vz;
                s[i*4+3] += vw; q[i*4+3] += vw * vw;
            } else {
                s[i*4+0] += crr * vx; q[i*4+0] += crr * (vx * vx);
                s[i*4+1] += crr * vy; q[i*4+1] += crr * (vy * vy);
                s[i*4+2] += crr * vz; q[i*4+2] += crr * (vz * vz);
                s[i*4+3] += crr * vw; q[i*4+3] += crr * (vw * vw);
            }
        }
    }

    // exchange partials among the 4 warps
#pragma unroll
    for (int e = 0; e < 16; e++) {
        sPart[w][0][e * 32 + lane] = s[e];
        sPart[w][1][e * 32 + lane] = q[e];
    }
    if (MODE != 0) sRs[w][lane] = rs;
    __syncthreads();

    const float rs_t = (MODE == 0) ? 4.5f
                     : (sRs[0][lane] + sRs[1][lane] + sRs[2][lane] + sRs[3][lane]);
    const float inv  = (MODE == 0) ? (1.f / 144.f) : (1.f / rs_t);

    float mean[16];                 // only live in MODE 2
    float i2v[16], t2[16];          // only live in MODE 0/1
    float l = 0.f, Kc = 0.f;
#pragma unroll
    for (int e = 0; e < 16; e++) {
        float se = sPart[0][0][e * 32 + lane] + sPart[1][0][e * 32 + lane]
                 + sPart[2][0][e * 32 + lane] + sPart[3][0][e * 32 + lane];
        float qe = sPart[0][1][e * 32 + lane] + sPart[1][1][e * 32 + lane]
                 + sPart[2][1][e * 32 + lane] + sPart[3][1][e * 32 + lane];
        float m = se * inv;
        float var = fmaxf(qe * inv - m * m, 1e-30f);
        l += __logf(sqrtf(var) + EPSF);
        if (MODE == 2) {
            mean[e] = m;
        } else {
            float y = 0.5f / var;
            i2v[e] = y * L2E;             // pre-scaled to log2 domain (E only)
            t2[e] = -2.f * m * y * L2E;
            Kc += m * m * y;
        }
    }
    const float cost = 16.f * beta_v[c] + rs_t * l;
    const float act = 1.f / (1.f + __expf(-lambd * (beta_a[c] - cost)));

    if (MODE == 2) {
        if (w == 0) {
            out[p * COUT + c] = act;
            float4* op = reinterpret_cast<float4*>(out + 28800 + (size_t)p * 512 + c * 16);
#pragma unroll
            for (int i = 0; i < 4; i++) {
                float4 m4 = { mean[i*4+0], mean[i*4+1], mean[i*4+2], mean[i*4+3] };
                op[i] = m4;
            }
        }
        return;
    }

    // ---- E step: recompute votes; zz2 = (zb - pe) in log2 units ----
    const float zb2 = (__logf(act + EPSF) - l - Kc) * L2E;
    float* zzb = g_zz + (size_t)p * 4608 + c;

#pragma unroll 2
    for (int nn = 0; nn < 36; nn++) {
        const int n = n0 + nn;
        const float4* q4 = W4 + n * 128;
        float4 cw0 = q4[0], cw1 = q4[32], cw2 = q4[64], cw3 = q4[96];

        const float4* Ap = reinterpret_cast<const float4*>(sA + n * 16);
        float pe = 0.f;
#pragma unroll
        for (int i = 0; i < 4; i++) {
            float4 a = Ap[i];
            float vx = a.x * cw0.x + a.y * cw1.x + a.z * cw2.x + a.w * cw3.x;
            float vy = a.x * cw0.y + a.y * cw1.y + a.z * cw2.y + a.w * cw3.y;
            float vz = a.x * cw0.z + a.y * cw1.z + a.z * cw2.z + a.w * cw3.z;
            float vw = a.x * cw0.w + a.y * cw1.w + a.z * cw2.w + a.w * cw3.w;
            pe += vx * fmaf(vx, i2v[i*4+0], t2[i*4+0]);
            pe += vy * fmaf(vy, i2v[i*4+1], t2[i*4+1]);
            pe += vz * fmaf(vz, i2v[i*4+2], t2[i*4+2]);
            pe += vw * fmaf(vw, i2v[i*4+3], t2[i*4+3]);
        }
        zzb[n * 32] = zb2 - pe;
    }
}

// Softmax normalizer over parent axis p for every (n,c) on layout [p][n][c].
// Writes only C2[n][c] = max2 + log2(sum exp2(zz2 - max2)).
// One block per n (144), 1024 threads = 32 c x 32 p-stripes.
__global__ void __launch_bounds__(1024) colog_kernel()
{
    __shared__ float red[32 * 33];
    __shared__ float gv[32];
    const int n = blockIdx.x;
    const int t = threadIdx.x;
    const int c = t & 31, st = t >> 5;
    const int base = n * 32 + c;

    float m = -1e30f;
    for (int p = st; p < P_TOT; p += 32)
        m = fmaxf(m, g_zz[(size_t)p * 4608 + base]);
    red[st * 33 + c] = m;
    __syncthreads();
    if (t < 32) {
        float M = red[t];
#pragma unroll
        for (int i = 1; i < 32; i++) M = fmaxf(M, red[i * 33 + t]);
        gv[t] = M;
    }
    __syncthreads();
    const float M = gv[c];

    float s = 0.f;
    for (int p = st; p < P_TOT; p += 32)
        s += ex2(g_zz[(size_t)p * 4608 + base] - M);
    red[st * 33 + c] = s;
    __syncthreads();
    if (t < 32) {
        float S = 0.f;
#pragma unroll
        for (int i = 0; i < 32; i++) S += red[i * 33 + t];
        g_C2[n * 32 + t] = gv[t] + lg2(S);
    }
}

extern "C" void kernel_launch(void* const* d_in, const int* in_sizes, int n_in,
                              void* d_out, int out_size)
{
    const float* pose = (const float*)d_in[1];
    const float* W    = (const float*)d_in[2];
    const float* ba   = (const float*)d_in[3];
    const float* bv   = (const float*)d_in[4];
    float* out = (float*)d_out;

    wtrans_kernel<<<72, 256>>>(W);
    me_kernel<0><<<P_TOT, 128>>>(pose, ba, bv, out, 0.0f);
    colog_kernel<<<NCH, 1024>>>();
    me_kernel<1><<<P_TOT, 128>>>(pose, ba, bv, out, 0.0005f);
    colog_kernel<<<NCH, 1024>>>();
    me_kernel<2><<<P_TOT, 128>>>(pose, ba, bv, out, 0.000975f);
}

// round 15
// speedup vs baseline: 1.0978x; 1.0978x over previous
#include <cuda_runtime.h>

#define EPSF 1e-7f
#define P_TOT 900
#define NCH 144
#define COUT 32
#define L2E 1.4426950408889634f

// Scratch (no allocations allowed)
static __device__ float g_zz[P_TOT * NCH * COUT];   // [p][n][c], log2-scaled
static __device__ float g_C2[NCH * COUT];           // per-(n,c) softmax log2-normalizer
static __device__ float g_W4[NCH * COUT * 16];      // [n][k][c][j] coalesced

__device__ __forceinline__ float ex2(float x) {
    float r; asm("ex2.approx.f32 %0,%1;" : "=f"(r) : "f"(x)); return r;
}
__device__ __forceinline__ float lg2(float x) {
    float r; asm("lg2.approx.f32 %0,%1;" : "=f"(r) : "f"(x)); return r;
}

// W[(n*32+c)*16 + k*4 + j] -> W4[((n*4+k)*32 + c)*4 + j]
__global__ void __launch_bounds__(256) wtrans_kernel(const float* __restrict__ W) {
    int t = blockIdx.x * 256 + threadIdx.x;   // over 144*32*4 float4 rows
    if (t < NCH * COUT * 4) {
        int k = t & 3, c = (t >> 2) & 31, n = t >> 7;
        float4 v = reinterpret_cast<const float4*>(W)[t];
        reinterpret_cast<float4*>(g_W4)[(n * 4 + k) * 32 + c] = v;
    }
}

extern __shared__ float dsm[];
// layout: sA     [2][2304]            (0    .. 4608)
//         sPart  [4][2][2][512]       (4608 .. 12800)
//         sRs    [4][2][32]           (12800.. 13056)
#define SA(par, idx)            dsm[(par) * 2304 + (idx)]
#define SPART(w_, par, sq, idx) dsm[4608 + ((((w_) * 2 + (par)) * 2 + (sq)) * 512) + (idx)]
#define SRS(w_, par, ln)        dsm[12800 + ((w_) * 2 + (par)) * 32 + (ln)]

// CTA = 128 threads = 4 warps = TWO parents; warp w handles children
// n in [36w, 36w+36) for BOTH parents, reusing each W row (4 coalesced
// LDG.128) for two parents' vote math -> W wavefronts per parent halved.
// Grid 450 @ 4 CTAs/SM = single wave, no tail.
// rr is never materialized: rr = ex2(zz2 - C2) on the MUFU pipe.
// MODE 0: rr uniform. MODE 1: rr on the fly, M+E. MODE 2: M only, outputs.
template<int MODE>
__global__ void __launch_bounds__(128, 4) me_kernel(
    const float* __restrict__ pose,
    const float* __restrict__ beta_a, const float* __restrict__ beta_v,
    float* __restrict__ out, float lambd)
{
    const int t = threadIdx.x;
    const int lane = t & 31, w = t >> 5;
    const int pb = blockIdx.x * 2;

    // gather child poses for both parents (float4, 64B rows)
    for (int idx = t; idx < 2 * NCH * 4; idx += 128) {
        int par = idx / 576, r = idx - par * 576;
        int n = r >> 2, vq = r & 3;
        int p = pb + par;
        int pr = p / 30, pcl = p % 30;
        int k = n >> 4, ci = n & 15;
        int q = (pr + k / 3) * 32 + pcl + (k % 3);
        float4 val = reinterpret_cast<const float4*>(pose + q * 256 + ci * 16)[vq];
        *reinterpret_cast<float4*>(&SA(par, n * 16 + vq * 4)) = val;
    }
    __syncthreads();

    const int c = lane;
    const float4* W4 = reinterpret_cast<const float4*>(g_W4) + c;   // + n*128 + k*32
    const float* zzr0 = g_zz + (size_t)pb * 4608 + lane;            // + n*32
    const float* zzr1 = zzr0 + 4608;
    const float* c2r = g_C2 + lane;                                 // + n*32
    const int n0 = w * 36;

    // ---- M step: W-prefetch pipelined, both parents per W row ----
    float s0[16], q0[16], s1[16], q1[16];
#pragma unroll
    for (int e = 0; e < 16; e++) { s0[e] = 0.f; q0[e] = 0.f; s1[e] = 0.f; q1[e] = 0.f; }
    float rs0 = 0.f, rs1 = 0.f;

    float4 cw0, cw1, cw2, cw3;
    {
        const float4* q4 = W4 + n0 * 128;
        cw0 = q4[0]; cw1 = q4[32]; cw2 = q4[64]; cw3 = q4[96];
    }

#pragma unroll 1
    for (int nn = 0; nn < 36; nn++) {
        const int n = n0 + nn;
        const int np = (nn < 35) ? n + 1 : n;
        const float4* q4n = W4 + np * 128;
        float4 nw0 = q4n[0], nw1 = q4n[32], nw2 = q4n[64], nw3 = q4n[96];

        float crr0, crr1;
        if (MODE != 0) {
            float c2v = __ldg(c2r + n * 32);
            crr0 = ex2(__ldg(zzr0 + n * 32) - c2v);
            crr1 = ex2(__ldg(zzr1 + n * 32) - c2v);
            rs0 += crr0; rs1 += crr1;
        }
        const float4* Ap0 = reinterpret_cast<const float4*>(&SA(0, n * 16));
        const float4* Ap1 = reinterpret_cast<const float4*>(&SA(1, n * 16));
#pragma unroll
        for (int i = 0; i < 4; i++) {
            float4 a = Ap0[i];
            float vx = a.x * cw0.x + a.y * cw1.x + a.z * cw2.x + a.w * cw3.x;
            float vy = a.x * cw0.y + a.y * cw1.y + a.z * cw2.y + a.w * cw3.y;
            float vz = a.x * cw0.z + a.y * cw1.z + a.z * cw2.z + a.w * cw3.z;
            float vw = a.x * cw0.w + a.y * cw1.w + a.z * cw2.w + a.w * cw3.w;
            if (MODE == 0) {
                s0[i*4+0] += vx; q0[i*4+0] += vx * vx;
                s0[i*4+1] += vy; q0[i*4+1] += vy * vy;
                s0[i*4+2] += vz; q0[i*4+2] += vz * vz;
                s0[i*4+3] += vw; q0[i*4+3] += vw * vw;
            } else {
                s0[i*4+0] += crr0 * vx; q0[i*4+0] += crr0 * (vx * vx);
                s0[i*4+1] += crr0 * vy; q0[i*4+1] += crr0 * (vy * vy);
                s0[i*4+2] += crr0 * vz; q0[i*4+2] += crr0 * (vz * vz);
                s0[i*4+3] += crr0 * vw; q0[i*4+3] += crr0 * (vw * vw);
            }
            float4 b = Ap1[i];
            float ux = b.x * cw0.x + b.y * cw1.x + b.z * cw2.x + b.w * cw3.x;
            float uy = b.x * cw0.y + b.y * cw1.y + b.z * cw2.y + b.w * cw3.y;
            float uz = b.x * cw0.z + b.y * cw1.z + b.z * cw2.z + b.w * cw3.z;
            float uw = b.x * cw0.w + b.y * cw1.w + b.z * cw2.w + b.w * cw3.w;
            if (MODE == 0) {
                s1[i*4+0] += ux; q1[i*4+0] += ux * ux;
                s1[i*4+1] += uy; q1[i*4+1] += uy * uy;
                s1[i*4+2] += uz; q1[i*4+2] += uz * uz;
                s1[i*4+3] += uw; q1[i*4+3] += uw * uw;
            } else {
                s1[i*4+0] += crr1 * ux; q1[i*4+0] += crr1 * (ux * ux);
                s1[i*4+1] += crr1 * uy; q1[i*4+1] += crr1 * (uy * uy);
                s1[i*4+2] += crr1 * uz; q1[i*4+2] += crr1 * (uz * uz);
                s1[i*4+3] += crr1 * uw; q1[i*4+3] += crr1 * (uw * uw);
            }
        }
        cw0 = nw0; cw1 = nw1; cw2 = nw2; cw3 = nw3;
    }

    // exchange partials among the 4 warps
#pragma unroll
    for (int e = 0; e < 16; e++) {
        SPART(w, 0, 0, e * 32 + lane) = s0[e];
        SPART(w, 0, 1, e * 32 + lane) = q0[e];
        SPART(w, 1, 0, e * 32 + lane) = s1[e];
        SPART(w, 1, 1, e * 32 + lane) = q1[e];
    }
    if (MODE != 0) { SRS(w, 0, lane) = rs0; SRS(w, 1, lane) = rs1; }
    __syncthreads();

    float i2v[2][16], t2[2][16], zb2[2];
#pragma unroll
    for (int par = 0; par < 2; par++) {
        const float rs_t = (MODE == 0) ? 4.5f
                         : (SRS(0, par, lane) + SRS(1, par, lane)
                          + SRS(2, par, lane) + SRS(3, par, lane));
        const float inv = (MODE == 0) ? (1.f / 144.f) : (1.f / rs_t);

        float mean[16];                 // only live in MODE 2
        float l = 0.f, Kc = 0.f;
#pragma unroll
        for (int e = 0; e < 16; e++) {
            float se = SPART(0, par, 0, e * 32 + lane) + SPART(1, par, 0, e * 32 + lane)
                     + SPART(2, par, 0, e * 32 + lane) + SPART(3, par, 0, e * 32 + lane);
            float qe = SPART(0, par, 1, e * 32 + lane) + SPART(1, par, 1, e * 32 + lane)
                     + SPART(2, par, 1, e * 32 + lane) + SPART(3, par, 1, e * 32 + lane);
            float m = se * inv;
            float var = fmaxf(qe * inv - m * m, 1e-30f);
            l += __logf(sqrtf(var) + EPSF);
            if (MODE == 2) {
                mean[e] = m;
            } else {
                float y = 0.5f / var;
                i2v[par][e] = y * L2E;
                t2[par][e] = -2.f * m * y * L2E;
                Kc += m * m * y;
            }
        }
        const float cost = 16.f * beta_v[c] + rs_t * l;
        const float act = 1.f / (1.f + __expf(-lambd * (beta_a[c] - cost)));

        if (MODE == 2) {
            if (w == 0) {
                const int p = pb + par;
                out[p * COUT + c] = act;
                float4* op = reinterpret_cast<float4*>(out + 28800 + (size_t)p * 512 + c * 16);
#pragma unroll
                for (int i = 0; i < 4; i++) {
                    float4 m4 = { mean[i*4+0], mean[i*4+1], mean[i*4+2], mean[i*4+3] };
                    op[i] = m4;
                }
            }
        } else {
            zb2[par] = (__logf(act + EPSF) - l - Kc) * L2E;
        }
    }
    if (MODE == 2) return;

    // ---- E step: both parents per W row; zz2 = zb2 - pe (log2 units) ----
    float* zzb0 = g_zz + (size_t)pb * 4608 + c;
    float* zzb1 = zzb0 + 4608;

    {
        const float4* q4 = W4 + n0 * 128;
        cw0 = q4[0]; cw1 = q4[32]; cw2 = q4[64]; cw3 = q4[96];
    }
#pragma unroll 1
    for (int nn = 0; nn < 36; nn++) {
        const int n = n0 + nn;
        const int np = (nn < 35) ? n + 1 : n;
        const float4* q4n = W4 + np * 128;
        float4 nw0 = q4n[0], nw1 = q4n[32], nw2 = q4n[64], nw3 = q4n[96];

        const float4* Ap0 = reinterpret_cast<const float4*>(&SA(0, n * 16));
        const float4* Ap1 = reinterpret_cast<const float4*>(&SA(1, n * 16));
        float pe0 = 0.f, pe1 = 0.f;
#pragma unroll
        for (int i = 0; i < 4; i++) {
            float4 a = Ap0[i];
            float vx = a.x * cw0.x + a.y * cw1.x + a.z * cw2.x + a.w * cw3.x;
            float vy = a.x * cw0.y + a.y * cw1.y + a.z * cw2.y + a.w * cw3.y;
            float vz = a.x * cw0.z + a.y * cw1.z + a.z * cw2.z + a.w * cw3.z;
            float vw = a.x * cw0.w + a.y * cw1.w + a.z * cw2.w + a.w * cw3.w;
            pe0 += vx * fmaf(vx, i2v[0][i*4+0], t2[0][i*4+0]);
            pe0 += vy * fmaf(vy, i2v[0][i*4+1], t2[0][i*4+1]);
            pe0 += vz * fmaf(vz, i2v[0][i*4+2], t2[0][i*4+2]);
            pe0 += vw * fmaf(vw, i2v[0][i*4+3], t2[0][i*4+3]);
            float4 b = Ap1[i];
            float ux = b.x * cw0.x + b.y * cw1.x + b.z * cw2.x + b.w * cw3.x;
            float uy = b.x * cw0.y + b.y * cw1.y + b.z * cw2.y + b.w * cw3.y;
            float uz = b.x * cw0.z + b.y * cw1.z + b.z * cw2.z + b.w * cw3.z;
            float uw = b.x * cw0.w + b.y * cw1.w + b.z * cw2.w + b.w * cw3.w;
            pe1 += ux * fmaf(ux, i2v[1][i*4+0], t2[1][i*4+0]);
            pe1 += uy * fmaf(uy, i2v[1][i*4+1], t2[1][i*4+1]);
            pe1 += uz * fmaf(uz, i2v[1][i*4+2], t2[1][i*4+2]);
            pe1 += uw * fmaf(uw, i2v[1][i*4+3], t2[1][i*4+3]);
        }
        zzb0[n * 32] = zb2[0] - pe0;
        zzb1[n * 32] = zb2[1] - pe1;
        cw0 = nw0; cw1 = nw1; cw2 = nw2; cw3 = nw3;
    }
}

// Softmax normalizer over parent axis p for every (n,c) on layout [p][n][c].
// Writes only C2[n][c] = max2 + log2(sum exp2(zz2 - max2)).
// One block per n (144), 1024 threads = 32 c x 32 p-stripes.
__global__ void __launch_bounds__(1024) colog_kernel()
{
    __shared__ float red[32 * 33];
    __shared__ float gv[32];
    const int n = blockIdx.x;
    const int t = threadIdx.x;
    const int c = t & 31, st = t >> 5;
    const int base = n * 32 + c;

    float m = -1e30f;
    for (int p = st; p < P_TOT; p += 32)
        m = fmaxf(m, g_zz[(size_t)p * 4608 + base]);
    red[st * 33 + c] = m;
    __syncthreads();
    if (t < 32) {
        float M = red[t];
#pragma unroll
        for (int i = 1; i < 32; i++) M = fmaxf(M, red[i * 33 + t]);
        gv[t] = M;
    }
    __syncthreads();
    const float M = gv[c];

    float s = 0.f;
    for (int p = st; p < P_TOT; p += 32)
        s += ex2(g_zz[(size_t)p * 4608 + base] - M);
    red[st * 33 + c] = s;
    __syncthreads();
    if (t < 32) {
        float S = 0.f;
#pragma unroll
        for (int i = 0; i < 32; i++) S += red[i * 33 + t];
        g_C2[n * 32 + t] = gv[t] + lg2(S);
    }
}

extern "C" void kernel_launch(void* const* d_in, const int* in_sizes, int n_in,
                              void* d_out, int out_size)
{
    const float* pose = (const float*)d_in[1];
    const float* W    = (const float*)d_in[2];
    const float* ba   = (const float*)d_in[3];
    const float* bv   = (const float*)d_in[4];
    float* out = (float*)d_out;

    const size_t shmem = 13056 * sizeof(float);   // 52224 B
    cudaFuncSetAttribute(me_kernel<0>, cudaFuncAttributeMaxDynamicSharedMemorySize, (int)shmem);
    cudaFuncSetAttribute(me_kernel<1>, cudaFuncAttributeMaxDynamicSharedMemorySize, (int)shmem);
    cudaFuncSetAttribute(me_kernel<2>, cudaFuncAttributeMaxDynamicSharedMemorySize, (int)shmem);

    wtrans_kernel<<<72, 256>>>(W);
    me_kernel<0><<<450, 128, shmem>>>(pose, ba, bv, out, 0.0f);
    colog_kernel<<<NCH, 1024>>>();
    me_kernel<1><<<450, 128, shmem>>>(pose, ba, bv, out, 0.0005f);
    colog_kernel<<<NCH, 1024>>>();
    me_kernel<2><<<450, 128, shmem>>>(pose, ba, bv, out, 0.000975f);
}

// round 16
// speedup vs baseline: 1.2025x; 1.0954x over previous
#include <cuda_runtime.h>

#define EPSF 1e-7f
#define P_TOT 900
#define NCH 144
#define COUT 32
#define L2E 1.4426950408889634f

// Scratch (no allocations allowed)
static __device__ float g_zz[P_TOT * NCH * COUT];   // [p][n][c], log2-scaled
static __device__ float g_C2[NCH * COUT];           // per-(n,c) softmax log2-normalizer
static __device__ float g_W4[NCH * COUT * 16];      // [n][k][c][j] coalesced

__device__ __forceinline__ float ex2(float x) {
    float r; asm("ex2.approx.f32 %0,%1;" : "=f"(r) : "f"(x)); return r;
}
__device__ __forceinline__ float lg2(float x) {
    float r; asm("lg2.approx.f32 %0,%1;" : "=f"(r) : "f"(x)); return r;
}

// W[(n*32+c)*16 + k*4 + j] -> W4[((n*4+k)*32 + c)*4 + j]
__global__ void __launch_bounds__(256) wtrans_kernel(const float* __restrict__ W) {
    int t = blockIdx.x * 256 + threadIdx.x;   // over 144*32*4 float4 rows
    if (t < NCH * COUT * 4) {
        int k = t & 3, c = (t >> 2) & 31, n = t >> 7;
        float4 v = reinterpret_cast<const float4*>(W)[t];
        reinterpret_cast<float4*>(g_W4)[(n * 4 + k) * 32 + c] = v;
    }
}

// CTA = 128 threads = 4 warps = ONE parent; warp w handles children
// n in [36w, 36w+36). lane = c. Per n each warp issues 4 fully coalesced
// LDG.128 (512B contiguous) from W4, software-pipelined (depth 1).
// rr is never materialized: rr = ex2(zz2 - C2) on the MUFU pipe.
// MODE 0: rr uniform (unweighted sums), M+E.
// MODE 1: rr on the fly, M+E.   MODE 2: rr on the fly, M only, outputs.
template<int MODE>
__global__ void __launch_bounds__(128, 4) me_kernel(
    const float* __restrict__ pose,
    const float* __restrict__ beta_a, const float* __restrict__ beta_v,
    float* __restrict__ out, float lambd)
{
    __shared__ float sA[NCH * 16];            // child poses
    __shared__ float sPart[4][2][512];        // [warp][s/q][e*32+c]
    __shared__ float sRs[4][32];              // [warp][c]

    const int t = threadIdx.x;
    const int lane = t & 31, w = t >> 5;
    const int p = blockIdx.x;
    const int pr = p / 30, pcl = p % 30;

    // gather child poses (float4, 64B rows)
    for (int idx = t; idx < NCH * 4; idx += 128) {
        int n = idx >> 2, vq = idx & 3;
        int k = n >> 4, ci = n & 15;
        int q = (pr + k / 3) * 32 + pcl + (k % 3);
        float4 val = reinterpret_cast<const float4*>(pose + q * 256 + ci * 16)[vq];
        *reinterpret_cast<float4*>(&sA[n * 16 + vq * 4]) = val;
    }
    __syncthreads();

    const int c = lane;
    const float4* W4 = reinterpret_cast<const float4*>(g_W4) + c;   // + n*128 + k*32
    const float* zzr = g_zz + (size_t)p * 4608 + lane;              // + n*32
    const float* c2r = g_C2 + lane;                                 // + n*32
    const int n0 = w * 36;

    // ---- M step: software-pipelined over 36 children ----
    float s[16], q[16];
#pragma unroll
    for (int e = 0; e < 16; e++) { s[e] = 0.f; q[e] = 0.f; }
    float rs = 0.f;

    float4 cw0, cw1, cw2, cw3;
    {
        const float4* q4 = W4 + n0 * 128;
        cw0 = q4[0]; cw1 = q4[32]; cw2 = q4[64]; cw3 = q4[96];
    }
    float carg = (MODE == 0) ? 0.f
               : (__ldg(zzr + n0 * 32) - __ldg(c2r + n0 * 32));

#pragma unroll 2
    for (int nn = 0; nn < 36; nn++) {
        const int n = n0 + nn;
        const int np = (n + 1 < 144) ? n + 1 : 143;
        const float4* q4n = W4 + np * 128;
        float4 nw0 = q4n[0], nw1 = q4n[32], nw2 = q4n[64], nw3 = q4n[96];
        float narg = (MODE == 0) ? 0.f
                   : (__ldg(zzr + np * 32) - __ldg(c2r + np * 32));

        const float4* Ap = reinterpret_cast<const float4*>(sA + n * 16);
        float crr;
        if (MODE != 0) { crr = ex2(carg); rs += crr; }
#pragma unroll
        for (int i = 0; i < 4; i++) {
            float4 a = Ap[i];
            float vx = a.x * cw0.x + a.y * cw1.x + a.z * cw2.x + a.w * cw3.x;
            float vy = a.x * cw0.y + a.y * cw1.y + a.z * cw2.y + a.w * cw3.y;
            float vz = a.x * cw0.z + a.y * cw1.z + a.z * cw2.z + a.w * cw3.z;
            float vw = a.x * cw0.w + a.y * cw1.w + a.z * cw2.w + a.w * cw3.w;
            if (MODE == 0) {
                s[i*4+0] += vx; q[i*4+0] += vx * vx;
                s[i*4+1] += vy; q[i*4+1] += vy * vy;
                s[i*4+2] += vz; q[i*4+2] += vz * vz;
                s[i*4+3] += vw; q[i*4+3] += vw * vw;
            } else {
                s[i*4+0] += crr * vx; q[i*4+0] += crr * (vx * vx);
                s[i*4+1] += crr * vy; q[i*4+1] += crr * (vy * vy);
                s[i*4+2] += crr * vz; q[i*4+2] += crr * (vz * vz);
                s[i*4+3] += crr * vw; q[i*4+3] += crr * (vw * vw);
            }
        }
        cw0 = nw0; cw1 = nw1; cw2 = nw2; cw3 = nw3; carg = narg;
    }

    // exchange partials among the 4 warps
#pragma unroll
    for (int e = 0; e < 16; e++) {
        sPart[w][0][e * 32 + lane] = s[e];
        sPart[w][1][e * 32 + lane] = q[e];
    }
    if (MODE != 0) sRs[w][lane] = rs;
    __syncthreads();

    const float rs_t = (MODE == 0) ? 4.5f
                     : (sRs[0][lane] + sRs[1][lane] + sRs[2][lane] + sRs[3][lane]);
    const float inv  = (MODE == 0) ? (1.f / 144.f) : (1.f / rs_t);

    float mean[16], i2v[16], t2[16];
    float l = 0.f, Kc = 0.f;
#pragma unroll
    for (int e = 0; e < 16; e++) {
        float se = sPart[0][0][e * 32 + lane] + sPart[1][0][e * 32 + lane]
                 + sPart[2][0][e * 32 + lane] + sPart[3][0][e * 32 + lane];
        float qe = sPart[0][1][e * 32 + lane] + sPart[1][1][e * 32 + lane]
                 + sPart[2][1][e * 32 + lane] + sPart[3][1][e * 32 + lane];
        float m = se * inv;
        mean[e] = m;
        float var = fmaxf(qe * inv - m * m, 1e-30f);
        l += __logf(sqrtf(var) + EPSF);
        float y = 0.5f / var;
        i2v[e] = y * L2E;             // pre-scaled to log2 domain (E only)
        t2[e] = -2.f * m * y * L2E;
        Kc += m * m * y;
    }
    const float cost = 16.f * beta_v[c] + rs_t * l;
    const float act = 1.f / (1.f + __expf(-lambd * (beta_a[c] - cost)));

    if (MODE == 2) {
        if (w == 0) {
            out[p * COUT + c] = act;
            float4* op = reinterpret_cast<float4*>(out + 28800 + (size_t)p * 512 + c * 16);
#pragma unroll
            for (int i = 0; i < 4; i++) {
                float4 m4 = { mean[i*4+0], mean[i*4+1], mean[i*4+2], mean[i*4+3] };
                op[i] = m4;
            }
        }
        return;
    }

    // ---- E step: recompute votes (pipelined); zz2 = (zb - pe) in log2 units
    const float zb2 = (__logf(act + EPSF) - l - Kc) * L2E;
    float* zzb = g_zz + (size_t)p * 4608 + c;

    {
        const float4* q4 = W4 + n0 * 128;
        cw0 = q4[0]; cw1 = q4[32]; cw2 = q4[64]; cw3 = q4[96];
    }
#pragma unroll 2
    for (int nn = 0; nn < 36; nn++) {
        const int n = n0 + nn;
        const int np = (n + 1 < 144) ? n + 1 : 143;
        const float4* q4n = W4 + np * 128;
        float4 nw0 = q4n[0], nw1 = q4n[32], nw2 = q4n[64], nw3 = q4n[96];

        const float4* Ap = reinterpret_cast<const float4*>(sA + n * 16);
        float pe = 0.f;
#pragma unroll
        for (int i = 0; i < 4; i++) {
            float4 a = Ap[i];
            float vx = a.x * cw0.x + a.y * cw1.x + a.z * cw2.x + a.w * cw3.x;
            float vy = a.x * cw0.y + a.y * cw1.y + a.z * cw2.y + a.w * cw3.y;
            float vz = a.x * cw0.z + a.y * cw1.z + a.z * cw2.z + a.w * cw3.z;
            float vw = a.x * cw0.w + a.y * cw1.w + a.z * cw2.w + a.w * cw3.w;
            pe += vx * fmaf(vx, i2v[i*4+0], t2[i*4+0]);
            pe += vy * fmaf(vy, i2v[i*4+1], t2[i*4+1]);
            pe += vz * fmaf(vz, i2v[i*4+2], t2[i*4+2]);
            pe += vw * fmaf(vw, i2v[i*4+3], t2[i*4+3]);
        }
        zzb[n * 32] = zb2 - pe;
        cw0 = nw0; cw1 = nw1; cw2 = nw2; cw3 = nw3;
    }
}

// Softmax normalizer over parent axis p for every (n,c) on layout [p][n][c].
// Writes only C2[n][c] = max2 + log2(sum exp2(zz2 - max2)).
// One block per n (144), 1024 threads: c4 = t&7 (float4 group of 4 c),
// st = t>>3 (128 p-stripes). Reads are float4, 100% sector efficiency.
__global__ void __launch_bounds__(1024) colog_kernel()
{
    __shared__ float4 red4[1024];    // [st*8 + c4]
    __shared__ float gM[32];
    const int n = blockIdx.x;
    const int t = threadIdx.x;
    const int c4 = t & 7, st = t >> 3;
    const float4* zp = reinterpret_cast<const float4*>(g_zz + n * 32) + c4;
    // p stride in float4 units: 4608/4 = 1152

    // ---- pass 1: max over p ----
    float4 m4 = {-1e30f, -1e30f, -1e30f, -1e30f};
    for (int p = st; p < P_TOT; p += 128) {
        float4 z = zp[p * 1152];
        m4.x = fmaxf(m4.x, z.x); m4.y = fmaxf(m4.y, z.y);
        m4.z = fmaxf(m4.z, z.z); m4.w = fmaxf(m4.w, z.w);
    }
    red4[st * 8 + c4] = m4;
    __syncthreads();
    if (t < 32) {
        const float* rf = reinterpret_cast<const float*>(red4);
        float M = -1e30f;
        for (int s2 = 0; s2 < 128; s2++)
            M = fmaxf(M, rf[s2 * 32 + t]);
        gM[t] = M;
    }
    __syncthreads();
    const float4 Mv = *reinterpret_cast<const float4*>(&gM[c4 * 4]);

    // ---- pass 2: sum of exp2(z - M) over p (L2-hot re-read) ----
    float4 s4 = {0.f, 0.f, 0.f, 0.f};
    for (int p = st; p < P_TOT; p += 128) {
        float4 z = zp[p * 1152];
        s4.x += ex2(z.x - Mv.x); s4.y += ex2(z.y - Mv.y);
        s4.z += ex2(z.z - Mv.z); s4.w += ex2(z.w - Mv.w);
    }
    __syncthreads();
    red4[st * 8 + c4] = s4;
    __syncthreads();
    if (t < 32) {
        const float* rf = reinterpret_cast<const float*>(red4);
        float S = 0.f;
        for (int s2 = 0; s2 < 128; s2++)
            S += rf[s2 * 32 + t];
        g_C2[n * 32 + t] = gM[t] + lg2(S);
    }
}

extern "C" void kernel_launch(void* const* d_in, const int* in_sizes, int n_in,
                              void* d_out, int out_size)
{
    const float* pose = (const float*)d_in[1];
    const float* W    = (const float*)d_in[2];
    const float* ba   = (const float*)d_in[3];
    const float* bv   = (const float*)d_in[4];
    float* out = (float*)d_out;

    wtrans_kernel<<<72, 256>>>(W);
    me_kernel<0><<<P_TOT, 128>>>(pose, ba, bv, out, 0.0f);
    colog_kernel<<<NCH, 1024>>>();
    me_kernel<1><<<P_TOT, 128>>>(pose, ba, bv, out, 0.0005f);
    colog_kernel<<<NCH, 1024>>>();
    me_kernel<2><<<P_TOT, 128>>>(pose, ba, bv, out, 0.000975f);
}